// round 1
// baseline (speedup 1.0000x reference)
#include <cuda_runtime.h>
#include <math.h>

#define BB     8192
#define OPTN   16
#define SHRD   22
#define UNIQN  8
#define OBSW   (SHRD + OPTN * UNIQN)   /* 150 */
#define MROWS  (BB * OPTN)             /* 131072 */

// ---------------- scratch (device globals; no allocation allowed) -------------
__device__ float g_se[BB * 256];               // 8 MB
__device__ float g_ue[MROWS * 128];            // 64 MB
__device__ float g_t1[(size_t)MROWS * 512];    // 256 MB
__device__ float g_t2[(size_t)MROWS * 256];    // 128 MB
__device__ float g_sw1t[22 * 256];
__device__ float g_sw2t[256 * 256];
__device__ float g_uw1t[8 * 128];
__device__ float g_uw2t[128 * 128];
__device__ float g_tw1t[384 * 512];
__device__ float g_tw2t[512 * 256];

// ---------------- prep: transpose all weights to [K][N] ----------------------
__global__ __launch_bounds__(256) void prep_kernel(
    const float* __restrict__ sw1, const float* __restrict__ sw2,
    const float* __restrict__ uw1, const float* __restrict__ uw2,
    const float* __restrict__ tw1, const float* __restrict__ tw2)
{
    int idx = blockIdx.x * 256 + threadIdx.x;
    if (idx < 512 * 384) { int n = idx / 384, k = idx - n * 384; g_tw1t[k * 512 + n] = tw1[idx]; }
    if (idx < 256 * 512) { int n = idx / 512, k = idx - n * 512; g_tw2t[k * 256 + n] = tw2[idx]; }
    if (idx < 256 * 256) { int o = idx / 256, k = idx - o * 256; g_sw2t[k * 256 + o] = sw2[idx]; }
    if (idx < 256 * 22)  { int o = idx / 22,  i = idx - o * 22;  g_sw1t[i * 256 + o] = sw1[idx]; }
    if (idx < 128 * 128) { int o = idx / 128, k = idx - o * 128; g_uw2t[k * 128 + o] = uw2[idx]; }
    if (idx < 128 * 8)   { int o = idx / 8,   i = idx - o * 8;   g_uw1t[i * 128 + o] = uw1[idx]; }
}

// ---------------- shared-branch MLP: obs[:, :22] -> 256 -> 256 ---------------
__global__ __launch_bounds__(256) void se_kernel(
    const float* __restrict__ obs,
    const float* __restrict__ sb1, const float* __restrict__ sb2)
{
    __shared__ float xs[32][SHRD];
    __shared__ float h1[32][256];
    const int t = threadIdx.x;
    const int row0 = blockIdx.x * 32;

    for (int l = t; l < 32 * SHRD; l += 256) {
        int r = l / SHRD, c = l - r * SHRD;
        xs[r][c] = obs[(size_t)(row0 + r) * OBSW + c];
    }
    __syncthreads();

    float acc[32];
#pragma unroll
    for (int r = 0; r < 32; ++r) acc[r] = 0.f;
    for (int i = 0; i < SHRD; ++i) {
        float wv = g_sw1t[i * 256 + t];
#pragma unroll
        for (int r = 0; r < 32; ++r) acc[r] += wv * xs[r][i];
    }
    float b1 = sb1[t];
#pragma unroll
    for (int r = 0; r < 32; ++r) h1[r][t] = fmaxf(acc[r] + b1, 0.f);
    __syncthreads();

#pragma unroll
    for (int r = 0; r < 32; ++r) acc[r] = 0.f;
    for (int k = 0; k < 256; ++k) {
        float wv = g_sw2t[k * 256 + t];
#pragma unroll
        for (int r = 0; r < 32; ++r) acc[r] += wv * h1[r][k];
    }
    float b2 = sb2[t];
#pragma unroll
    for (int r = 0; r < 32; ++r)
        g_se[(size_t)(row0 + r) * 256 + t] = fmaxf(acc[r] + b2, 0.f);
}

// ---------------- unique-branch MLP: (B*OPT, 8) -> 128 -> 128 + mask ---------
__global__ __launch_bounds__(128) void ue_kernel(
    const float* __restrict__ obs,
    const float* __restrict__ ub1, const float* __restrict__ ub2,
    const float* __restrict__ noop)
{
    __shared__ float xs[32][UNIQN];
    __shared__ float h1[32][128];
    const int t = threadIdx.x;
    const int m0 = blockIdx.x * 32;

    for (int l = t; l < 32 * UNIQN; l += 128) {
        int r = l >> 3, c = l & 7;
        int m = m0 + r;
        xs[r][c] = obs[(size_t)(m >> 4) * OBSW + SHRD + (m & 15) * UNIQN + c];
    }
    __syncthreads();

    float acc[32];
#pragma unroll
    for (int r = 0; r < 32; ++r) acc[r] = 0.f;
#pragma unroll
    for (int i = 0; i < UNIQN; ++i) {
        float wv = g_uw1t[i * 128 + t];
#pragma unroll
        for (int r = 0; r < 32; ++r) acc[r] += wv * xs[r][i];
    }
    float b1 = ub1[t];
#pragma unroll
    for (int r = 0; r < 32; ++r) h1[r][t] = fmaxf(acc[r] + b1, 0.f);
    __syncthreads();

#pragma unroll
    for (int r = 0; r < 32; ++r) acc[r] = 0.f;
    for (int k = 0; k < 128; ++k) {
        float wv = g_uw2t[k * 128 + t];
#pragma unroll
        for (int r = 0; r < 32; ++r) acc[r] += wv * h1[r][k];
    }
    float b2 = ub2[t];
    float ne = noop[t];
#pragma unroll
    for (int r = 0; r < 32; ++r) {
        float v = fmaxf(acc[r] + b2, 0.f);
        if (xs[r][0] == 1.0f) v = ne;
        g_ue[(size_t)(m0 + r) * 128 + t] = v;
    }
}

// ---------------- trunk GEMM: C = relu(A @ Wt + b) ---------------------------
// FIRST: A = [se | ue] gather (K=384, N=512) -> g_t1
// !FIRST: A = g_t1 (K=512, N=256)           -> g_t2
template <bool FIRST>
__global__ __launch_bounds__(256) void trunk_kernel(const float* __restrict__ bias)
{
    constexpr int KDIM = FIRST ? 384 : 512;
    constexpr int NDIM = FIRST ? 512 : 256;
    const float* __restrict__ Bt   = FIRST ? g_tw1t : g_tw2t;
    float* __restrict__       Cout = FIRST ? g_t1   : g_t2;

    __shared__ __align__(16) float As[16][132];
    __shared__ __align__(16) float Bs[16][132];

    const int tid = threadIdx.x;
    const int tx = tid & 15, ty = tid >> 4;
    const int mBlock = blockIdx.y * 128;
    const int nBlock = blockIdx.x * 128;

    float acc[8][8] = {};

    // A load mapping: thread covers half a row (8 consecutive k) of one m-row
    const int am = tid >> 1;
    const int kh = (tid & 1) * 8;
    const int m  = mBlock + am;
    const float* seRow = g_se + (size_t)(m >> 4) * 256;
    const float* ueRow = g_ue + (size_t)m * 128;
    const float* aRow  = g_t1 + (size_t)m * 512;

    // B load mapping: 2 groups of 128 threads, each loads 8 k-rows of one n-col
    const int bn  = tid & 127;
    const int bkb = (tid >> 7) * 8;

    for (int k0 = 0; k0 < KDIM; k0 += 16) {
        const float* asrc;
        if (FIRST) {
            int k = k0 + kh;
            asrc = (k < 256) ? (seRow + k) : (ueRow + (k - 256));
        } else {
            asrc = aRow + k0 + kh;
        }
        float4 v0 = *reinterpret_cast<const float4*>(asrc);
        float4 v1 = *reinterpret_cast<const float4*>(asrc + 4);
        As[kh + 0][am] = v0.x; As[kh + 1][am] = v0.y;
        As[kh + 2][am] = v0.z; As[kh + 3][am] = v0.w;
        As[kh + 4][am] = v1.x; As[kh + 5][am] = v1.y;
        As[kh + 6][am] = v1.z; As[kh + 7][am] = v1.w;

        const float* bsrc = Bt + (size_t)(k0 + bkb) * NDIM + nBlock + bn;
#pragma unroll
        for (int j = 0; j < 8; ++j) Bs[bkb + j][bn] = bsrc[(size_t)j * NDIM];

        __syncthreads();
#pragma unroll
        for (int kk = 0; kk < 16; ++kk) {
            float4 a0 = *reinterpret_cast<const float4*>(&As[kk][ty * 8]);
            float4 a1 = *reinterpret_cast<const float4*>(&As[kk][ty * 8 + 4]);
            float4 b0 = *reinterpret_cast<const float4*>(&Bs[kk][tx * 8]);
            float4 b1 = *reinterpret_cast<const float4*>(&Bs[kk][tx * 8 + 4]);
            float a[8] = {a0.x, a0.y, a0.z, a0.w, a1.x, a1.y, a1.z, a1.w};
            float b[8] = {b0.x, b0.y, b0.z, b0.w, b1.x, b1.y, b1.z, b1.w};
#pragma unroll
            for (int i = 0; i < 8; ++i)
#pragma unroll
                for (int j = 0; j < 8; ++j)
                    acc[i][j] += a[i] * b[j];
        }
        __syncthreads();
    }

    const int nb = nBlock + tx * 8;
    float b8[8];
#pragma unroll
    for (int j = 0; j < 8; ++j) b8[j] = bias[nb + j];
#pragma unroll
    for (int i = 0; i < 8; ++i) {
        int mm = mBlock + ty * 8 + i;
        float* dst = Cout + (size_t)mm * NDIM + nb;
        float4 r0, r1;
        r0.x = fmaxf(acc[i][0] + b8[0], 0.f);
        r0.y = fmaxf(acc[i][1] + b8[1], 0.f);
        r0.z = fmaxf(acc[i][2] + b8[2], 0.f);
        r0.w = fmaxf(acc[i][3] + b8[3], 0.f);
        r1.x = fmaxf(acc[i][4] + b8[4], 0.f);
        r1.y = fmaxf(acc[i][5] + b8[5], 0.f);
        r1.z = fmaxf(acc[i][6] + b8[6], 0.f);
        r1.w = fmaxf(acc[i][7] + b8[7], 0.f);
        *reinterpret_cast<float4*>(dst)     = r0;
        *reinterpret_cast<float4*>(dst + 4) = r1;
    }
}

// ---------------- heads: warp per row, dual dot + sigmoid --------------------
__global__ __launch_bounds__(256) void head_kernel(
    const float* __restrict__ vw, const float* __restrict__ vb,
    const float* __restrict__ dw, const float* __restrict__ db,
    float* __restrict__ out)
{
    const int warp = blockIdx.x * 8 + (threadIdx.x >> 5);
    const int lane = threadIdx.x & 31;
    if (warp >= MROWS) return;
    const float* row = g_t2 + (size_t)warp * 256;
    float sv = 0.f, sd = 0.f;
#pragma unroll
    for (int j = 0; j < 8; ++j) {
        int c = lane + 32 * j;
        float t = row[c];
        sv += t * vw[c];
        sd += t * dw[c];
    }
#pragma unroll
    for (int off = 16; off > 0; off >>= 1) {
        sv += __shfl_xor_sync(0xffffffffu, sv, off);
        sd += __shfl_xor_sync(0xffffffffu, sd, off);
    }
    if (lane == 0) {
        out[warp] = sv + vb[0];
        float s = sd + db[0];
        out[MROWS + warp] = 1.f / (1.f + expf(-s)) * 0.4f + 0.1f;
    }
}

// ---------------- launch -----------------------------------------------------
extern "C" void kernel_launch(void* const* d_in, const int* in_sizes, int n_in,
                              void* d_out, int out_size)
{
    (void)in_sizes; (void)n_in; (void)out_size;
    const float* obs  = (const float*)d_in[0];
    const float* sw1  = (const float*)d_in[1];
    const float* sb1  = (const float*)d_in[2];
    const float* sw2  = (const float*)d_in[3];
    const float* sb2  = (const float*)d_in[4];
    const float* uw1  = (const float*)d_in[5];
    const float* ub1  = (const float*)d_in[6];
    const float* uw2  = (const float*)d_in[7];
    const float* ub2  = (const float*)d_in[8];
    const float* noop = (const float*)d_in[9];
    const float* tw1  = (const float*)d_in[10];
    const float* tb1  = (const float*)d_in[11];
    const float* tw2  = (const float*)d_in[12];
    const float* tb2  = (const float*)d_in[13];
    const float* vw   = (const float*)d_in[14];
    const float* vb   = (const float*)d_in[15];
    const float* dw   = (const float*)d_in[16];
    const float* db   = (const float*)d_in[17];
    float* out = (float*)d_out;

    prep_kernel<<<768, 256>>>(sw1, sw2, uw1, uw2, tw1, tw2);
    se_kernel<<<BB / 32, 256>>>(obs, sb1, sb2);
    ue_kernel<<<MROWS / 32, 128>>>(obs, ub1, ub2, noop);
    trunk_kernel<true><<<dim3(4, MROWS / 128), 256>>>(tb1);
    trunk_kernel<false><<<dim3(2, MROWS / 128), 256>>>(tb2);
    head_kernel<<<MROWS / 8, 256>>>(vw, vb, dw, db, out);
}

// round 2
// speedup vs baseline: 1.9846x; 1.9846x over previous
#include <cuda_runtime.h>
#include <math.h>
#include <stdint.h>

#define BB     8192
#define OPTN   16
#define SHRD   22
#define UNIQN  8
#define OBSW   (SHRD + OPTN * UNIQN)   /* 150 */
#define MROWS  (BB * OPTN)             /* 131072 */

// ---------------- scratch (device globals; no allocation allowed) -------------
__device__ float g_se[BB * 256];               // 8 MB
__device__ float g_ue[MROWS * 128];            // 64 MB
__device__ float g_t1[(size_t)MROWS * 512];    // 256 MB
__device__ float g_t2[(size_t)MROWS * 256];    // 128 MB
__device__ float g_sw1t[22 * 256];
__device__ float g_sw2t[256 * 256];
__device__ float g_uw1t[8 * 128];
__device__ float g_uw2t[128 * 128];
__device__ float g_tw1t[384 * 512];
__device__ float g_tw2t[512 * 256];

__device__ __forceinline__ uint32_t f2tf32(float x) {
    uint32_t y;
    asm("cvt.rna.tf32.f32 %0, %1;" : "=r"(y) : "f"(x));
    return y;
}

__device__ __forceinline__ void mma_tf32(float* c, const uint32_t* a, const uint32_t* b) {
    asm volatile(
        "mma.sync.aligned.m16n8k8.row.col.f32.tf32.tf32.f32 "
        "{%0,%1,%2,%3}, {%4,%5,%6,%7}, {%8,%9}, {%0,%1,%2,%3};"
        : "+f"(c[0]), "+f"(c[1]), "+f"(c[2]), "+f"(c[3])
        : "r"(a[0]), "r"(a[1]), "r"(a[2]), "r"(a[3]), "r"(b[0]), "r"(b[1]));
}

// ---------------- prep: transpose all weights to [K][N] ----------------------
__global__ __launch_bounds__(256) void prep_kernel(
    const float* __restrict__ sw1, const float* __restrict__ sw2,
    const float* __restrict__ uw1, const float* __restrict__ uw2,
    const float* __restrict__ tw1, const float* __restrict__ tw2)
{
    int idx = blockIdx.x * 256 + threadIdx.x;
    if (idx < 512 * 384) { int n = idx / 384, k = idx - n * 384; g_tw1t[k * 512 + n] = tw1[idx]; }
    if (idx < 256 * 512) { int n = idx / 512, k = idx - n * 512; g_tw2t[k * 256 + n] = tw2[idx]; }
    if (idx < 256 * 256) { int o = idx / 256, k = idx - o * 256; g_sw2t[k * 256 + o] = sw2[idx]; }
    if (idx < 256 * 22)  { int o = idx / 22,  i = idx - o * 22;  g_sw1t[i * 256 + o] = sw1[idx]; }
    if (idx < 128 * 128) { int o = idx / 128, k = idx - o * 128; g_uw2t[k * 128 + o] = uw2[idx]; }
    if (idx < 128 * 8)   { int o = idx / 8,   i = idx - o * 8;   g_uw1t[i * 128 + o] = uw1[idx]; }
}

// ---------------- shared-branch MLP: obs[:, :22] -> 256 -> 256 ---------------
__global__ __launch_bounds__(256) void se_kernel(
    const float* __restrict__ obs,
    const float* __restrict__ sb1, const float* __restrict__ sb2)
{
    __shared__ float xs[32][SHRD];
    __shared__ float h1[32][256];
    const int t = threadIdx.x;
    const int row0 = blockIdx.x * 32;

    for (int l = t; l < 32 * SHRD; l += 256) {
        int r = l / SHRD, c = l - r * SHRD;
        xs[r][c] = obs[(size_t)(row0 + r) * OBSW + c];
    }
    __syncthreads();

    float acc[32];
#pragma unroll
    for (int r = 0; r < 32; ++r) acc[r] = 0.f;
    for (int i = 0; i < SHRD; ++i) {
        float wv = g_sw1t[i * 256 + t];
#pragma unroll
        for (int r = 0; r < 32; ++r) acc[r] += wv * xs[r][i];
    }
    float b1 = sb1[t];
#pragma unroll
    for (int r = 0; r < 32; ++r) h1[r][t] = fmaxf(acc[r] + b1, 0.f);
    __syncthreads();

#pragma unroll
    for (int r = 0; r < 32; ++r) acc[r] = 0.f;
    for (int k = 0; k < 256; ++k) {
        float wv = g_sw2t[k * 256 + t];
#pragma unroll
        for (int r = 0; r < 32; ++r) acc[r] += wv * h1[r][k];
    }
    float b2 = sb2[t];
#pragma unroll
    for (int r = 0; r < 32; ++r)
        g_se[(size_t)(row0 + r) * 256 + t] = fmaxf(acc[r] + b2, 0.f);
}

// ---------------- unique-branch MLP: (B*OPT, 8) -> 128 -> 128 + mask ---------
__global__ __launch_bounds__(128) void ue_kernel(
    const float* __restrict__ obs,
    const float* __restrict__ ub1, const float* __restrict__ ub2,
    const float* __restrict__ noop)
{
    __shared__ float xs[32][UNIQN];
    __shared__ float h1[32][128];
    const int t = threadIdx.x;
    const int m0 = blockIdx.x * 32;

    for (int l = t; l < 32 * UNIQN; l += 128) {
        int r = l >> 3, c = l & 7;
        int m = m0 + r;
        xs[r][c] = obs[(size_t)(m >> 4) * OBSW + SHRD + (m & 15) * UNIQN + c];
    }
    __syncthreads();

    float acc[32];
#pragma unroll
    for (int r = 0; r < 32; ++r) acc[r] = 0.f;
#pragma unroll
    for (int i = 0; i < UNIQN; ++i) {
        float wv = g_uw1t[i * 128 + t];
#pragma unroll
        for (int r = 0; r < 32; ++r) acc[r] += wv * xs[r][i];
    }
    float b1 = ub1[t];
#pragma unroll
    for (int r = 0; r < 32; ++r) h1[r][t] = fmaxf(acc[r] + b1, 0.f);
    __syncthreads();

#pragma unroll
    for (int r = 0; r < 32; ++r) acc[r] = 0.f;
    for (int k = 0; k < 128; ++k) {
        float wv = g_uw2t[k * 128 + t];
#pragma unroll
        for (int r = 0; r < 32; ++r) acc[r] += wv * h1[r][k];
    }
    float b2 = ub2[t];
    float ne = noop[t];
#pragma unroll
    for (int r = 0; r < 32; ++r) {
        float v = fmaxf(acc[r] + b2, 0.f);
        if (xs[r][0] == 1.0f) v = ne;
        g_ue[(size_t)(m0 + r) * 128 + t] = v;
    }
}

// ---------------- trunk GEMM on tensor cores (tf32 mma) ----------------------
// FIRST: A = [se | ue] gather (K=384), N=512 -> g_t1
// !FIRST: A = g_t1 (K=512), N=256           -> g_t2
// Block 128x128, BK=16, 8 warps (2x4), warp 64x32, m16n8k8 tf32.
template <bool FIRST>
__global__ __launch_bounds__(256, 2) void gemm_tc(const float* __restrict__ bias)
{
    constexpr int KD = FIRST ? 384 : 512;
    constexpr int ND = FIRST ? 512 : 256;
    const float* __restrict__ Bt = FIRST ? g_tw1t : g_tw2t;
    float* __restrict__       C  = FIRST ? g_t1   : g_t2;

    constexpr int BM = 128, BN = 128, BK = 16, PAD = 8;
    constexpr int LDA = BM + PAD, LDB = BN + PAD;

    __shared__ uint32_t As[2][BK][LDA];
    __shared__ uint32_t Bs[2][BK][LDB];

    const int tid  = threadIdx.x;
    const int lane = tid & 31;
    const int wid  = tid >> 5;
    const int wm   = (wid >> 2) * 64;   // warp M offset
    const int wn   = (wid & 3) * 32;    // warp N offset
    const int mB   = blockIdx.y * BM;
    const int nB   = blockIdx.x * BN;
    const int gID  = lane >> 2;         // group id 0..7
    const int tIG  = lane & 3;          // thread-in-group 0..3

    float acc[4][4][4] = {};

    float4 va[2], vb[2];

    auto loadG = [&](int k0) {
#pragma unroll
        for (int j = 0; j < 2; ++j) {
            int idx = 2 * tid + j;
            int m = idx >> 2, kq = idx & 3;
            int k = k0 + kq * 4;
            int gm = mB + m;
            const float* p;
            if (FIRST) {
                p = (k < 256) ? (g_se + (size_t)(gm >> 4) * 256 + k)
                              : (g_ue + (size_t)gm * 128 + (k - 256));
            } else {
                p = g_t1 + (size_t)gm * 512 + k;
            }
            va[j] = *reinterpret_cast<const float4*>(p);

            int krow = idx >> 5, n4 = idx & 31;
            vb[j] = *reinterpret_cast<const float4*>(
                Bt + (size_t)(k0 + krow) * ND + nB + n4 * 4);
        }
    };
    auto storeS = [&](int buf) {
#pragma unroll
        for (int j = 0; j < 2; ++j) {
            int idx = 2 * tid + j;
            int m = idx >> 2, kq = idx & 3;
            As[buf][kq * 4 + 0][m] = f2tf32(va[j].x);
            As[buf][kq * 4 + 1][m] = f2tf32(va[j].y);
            As[buf][kq * 4 + 2][m] = f2tf32(va[j].z);
            As[buf][kq * 4 + 3][m] = f2tf32(va[j].w);
            int krow = idx >> 5, n4 = idx & 31;
            Bs[buf][krow][n4 * 4 + 0] = f2tf32(vb[j].x);
            Bs[buf][krow][n4 * 4 + 1] = f2tf32(vb[j].y);
            Bs[buf][krow][n4 * 4 + 2] = f2tf32(vb[j].z);
            Bs[buf][krow][n4 * 4 + 3] = f2tf32(vb[j].w);
        }
    };

    loadG(0);
    storeS(0);
    __syncthreads();

    constexpr int nIter = KD / BK;
    for (int it = 0; it < nIter; ++it) {
        const int cur = it & 1;
        if (it + 1 < nIter) loadG((it + 1) * BK);

#pragma unroll
        for (int kk = 0; kk < BK; kk += 8) {
            uint32_t af[4][4], bf[4][2];
#pragma unroll
            for (int mi = 0; mi < 4; ++mi) {
                int m0 = wm + mi * 16 + gID;
                af[mi][0] = As[cur][kk + tIG][m0];
                af[mi][1] = As[cur][kk + tIG][m0 + 8];
                af[mi][2] = As[cur][kk + tIG + 4][m0];
                af[mi][3] = As[cur][kk + tIG + 4][m0 + 8];
            }
#pragma unroll
            for (int ni = 0; ni < 4; ++ni) {
                int n0 = wn + ni * 8 + gID;
                bf[ni][0] = Bs[cur][kk + tIG][n0];
                bf[ni][1] = Bs[cur][kk + tIG + 4][n0];
            }
#pragma unroll
            for (int mi = 0; mi < 4; ++mi)
#pragma unroll
                for (int ni = 0; ni < 4; ++ni)
                    mma_tf32(acc[mi][ni], af[mi], bf[ni]);
        }

        if (it + 1 < nIter) storeS(cur ^ 1);
        __syncthreads();
    }

    // epilogue: bias + relu, float2 stores
#pragma unroll
    for (int mi = 0; mi < 4; ++mi) {
#pragma unroll
        for (int ni = 0; ni < 4; ++ni) {
            int mrow = mB + wm + mi * 16 + gID;
            int ncol = nB + wn + ni * 8 + 2 * tIG;
            float b0 = bias[ncol], b1 = bias[ncol + 1];
            float2 r0, r1;
            r0.x = fmaxf(acc[mi][ni][0] + b0, 0.f);
            r0.y = fmaxf(acc[mi][ni][1] + b1, 0.f);
            r1.x = fmaxf(acc[mi][ni][2] + b0, 0.f);
            r1.y = fmaxf(acc[mi][ni][3] + b1, 0.f);
            *reinterpret_cast<float2*>(C + (size_t)mrow * ND + ncol)       = r0;
            *reinterpret_cast<float2*>(C + (size_t)(mrow + 8) * ND + ncol) = r1;
        }
    }
}

// ---------------- heads: warp per row, dual dot + sigmoid --------------------
__global__ __launch_bounds__(256) void head_kernel(
    const float* __restrict__ vw, const float* __restrict__ vb,
    const float* __restrict__ dw, const float* __restrict__ db,
    float* __restrict__ out)
{
    const int warp = blockIdx.x * 8 + (threadIdx.x >> 5);
    const int lane = threadIdx.x & 31;
    if (warp >= MROWS) return;
    const float* row = g_t2 + (size_t)warp * 256;
    float sv = 0.f, sd = 0.f;
#pragma unroll
    for (int j = 0; j < 8; ++j) {
        int c = lane + 32 * j;
        float t = row[c];
        sv += t * vw[c];
        sd += t * dw[c];
    }
#pragma unroll
    for (int off = 16; off > 0; off >>= 1) {
        sv += __shfl_xor_sync(0xffffffffu, sv, off);
        sd += __shfl_xor_sync(0xffffffffu, sd, off);
    }
    if (lane == 0) {
        out[warp] = sv + vb[0];
        float s = sd + db[0];
        out[MROWS + warp] = 1.f / (1.f + expf(-s)) * 0.4f + 0.1f;
    }
}

// ---------------- launch -----------------------------------------------------
extern "C" void kernel_launch(void* const* d_in, const int* in_sizes, int n_in,
                              void* d_out, int out_size)
{
    (void)in_sizes; (void)n_in; (void)out_size;
    const float* obs  = (const float*)d_in[0];
    const float* sw1  = (const float*)d_in[1];
    const float* sb1  = (const float*)d_in[2];
    const float* sw2  = (const float*)d_in[3];
    const float* sb2  = (const float*)d_in[4];
    const float* uw1  = (const float*)d_in[5];
    const float* ub1  = (const float*)d_in[6];
    const float* uw2  = (const float*)d_in[7];
    const float* ub2  = (const float*)d_in[8];
    const float* noop = (const float*)d_in[9];
    const float* tw1  = (const float*)d_in[10];
    const float* tb1  = (const float*)d_in[11];
    const float* tw2  = (const float*)d_in[12];
    const float* tb2  = (const float*)d_in[13];
    const float* vw   = (const float*)d_in[14];
    const float* vb   = (const float*)d_in[15];
    const float* dw   = (const float*)d_in[16];
    const float* db   = (const float*)d_in[17];
    float* out = (float*)d_out;

    prep_kernel<<<768, 256>>>(sw1, sw2, uw1, uw2, tw1, tw2);
    se_kernel<<<BB / 32, 256>>>(obs, sb1, sb2);
    ue_kernel<<<MROWS / 32, 128>>>(obs, ub1, ub2, noop);
    gemm_tc<true><<<dim3(512 / 128, MROWS / 128), 256>>>(tb1);
    gemm_tc<false><<<dim3(256 / 128, MROWS / 128), 256>>>(tb2);
    head_kernel<<<MROWS / 8, 256>>>(vw, vb, dw, db, out);
}

// round 4
// speedup vs baseline: 2.9932x; 1.5082x over previous
#include <cuda_runtime.h>
#include <cuda_fp16.h>
#include <math.h>
#include <stdint.h>

#define BB     8192
#define OPTN   16
#define SHRD   22
#define UNIQN  8
#define OBSW   150
#define MROWS  131072

// ---------------- scratch (device globals) -----------------------------------
__device__ __half g_se_h[BB * 256];                 // 4 MB
__device__ __half g_ue_h[(size_t)MROWS * 128];      // 32 MB
__device__ __half g_t1h[(size_t)MROWS * 512];       // 128 MB
__device__ __half g_tw1h[512 * 384];                // fp16 weights, [n][k]
__device__ __half g_tw2h[256 * 512];
__device__ float  g_pv[2 * MROWS];                  // head partials
__device__ float  g_pd[2 * MROWS];
__device__ float  g_sw1t[22 * 256];
__device__ float  g_sw2t[256 * 256];
__device__ float  g_uw1t[8 * 128];
__device__ float  g_uw2t[128 * 128];

__device__ __forceinline__ void mma_f16(float* c, const uint32_t* a, const uint32_t* b) {
    asm volatile(
        "mma.sync.aligned.m16n8k16.row.col.f32.f16.f16.f32 "
        "{%0,%1,%2,%3}, {%4,%5,%6,%7}, {%8,%9}, {%0,%1,%2,%3};"
        : "+f"(c[0]), "+f"(c[1]), "+f"(c[2]), "+f"(c[3])
        : "r"(a[0]), "r"(a[1]), "r"(a[2]), "r"(a[3]), "r"(b[0]), "r"(b[1]));
}

__device__ __forceinline__ void ldmx4(uint32_t* r, uint32_t addr) {
    asm volatile("ldmatrix.sync.aligned.m8n8.x4.shared.b16 {%0,%1,%2,%3}, [%4];"
                 : "=r"(r[0]), "=r"(r[1]), "=r"(r[2]), "=r"(r[3]) : "r"(addr));
}

// ---------------- prep: fp16 weight copies + f32 transposes ------------------
__global__ __launch_bounds__(256) void prep_kernel(
    const float* __restrict__ sw1, const float* __restrict__ sw2,
    const float* __restrict__ uw1, const float* __restrict__ uw2,
    const float* __restrict__ tw1, const float* __restrict__ tw2)
{
    int idx = blockIdx.x * 256 + threadIdx.x;
    if (idx < 512 * 384) g_tw1h[idx] = __float2half(tw1[idx]);
    if (idx < 256 * 512) g_tw2h[idx] = __float2half(tw2[idx]);
    if (idx < 256 * 256) { int o = idx / 256, k = idx - o * 256; g_sw2t[k * 256 + o] = sw2[idx]; }
    if (idx < 256 * 22)  { int o = idx / 22,  i = idx - o * 22;  g_sw1t[i * 256 + o] = sw1[idx]; }
    if (idx < 128 * 128) { int o = idx / 128, k = idx - o * 128; g_uw2t[k * 128 + o] = uw2[idx]; }
    if (idx < 128 * 8)   { int o = idx / 8,   i = idx - o * 8;   g_uw1t[i * 128 + o] = uw1[idx]; }
}

// ---------------- shared-branch MLP (f32 math, fp16 out) ---------------------
__global__ __launch_bounds__(256) void se_kernel(
    const float* __restrict__ obs,
    const float* __restrict__ sb1, const float* __restrict__ sb2)
{
    __shared__ float xs[32][SHRD];
    __shared__ float h1[32][256];
    const int t = threadIdx.x;
    const int row0 = blockIdx.x * 32;

    for (int l = t; l < 32 * SHRD; l += 256) {
        int r = l / SHRD, c = l - r * SHRD;
        xs[r][c] = obs[(size_t)(row0 + r) * OBSW + c];
    }
    __syncthreads();

    float acc[32];
#pragma unroll
    for (int r = 0; r < 32; ++r) acc[r] = 0.f;
    for (int i = 0; i < SHRD; ++i) {
        float wv = g_sw1t[i * 256 + t];
#pragma unroll
        for (int r = 0; r < 32; ++r) acc[r] += wv * xs[r][i];
    }
    float b1 = sb1[t];
#pragma unroll
    for (int r = 0; r < 32; ++r) h1[r][t] = fmaxf(acc[r] + b1, 0.f);
    __syncthreads();

#pragma unroll
    for (int r = 0; r < 32; ++r) acc[r] = 0.f;
    for (int k = 0; k < 256; ++k) {
        float wv = g_sw2t[k * 256 + t];
#pragma unroll
        for (int r = 0; r < 32; ++r) acc[r] += wv * h1[r][k];
    }
    float b2 = sb2[t];
#pragma unroll
    for (int r = 0; r < 32; ++r)
        g_se_h[(size_t)(row0 + r) * 256 + t] = __float2half(fmaxf(acc[r] + b2, 0.f));
}

// ---------------- unique-branch MLP (f32 math, fp16 out) ---------------------
__global__ __launch_bounds__(128) void ue_kernel(
    const float* __restrict__ obs,
    const float* __restrict__ ub1, const float* __restrict__ ub2,
    const float* __restrict__ noop)
{
    __shared__ float xs[32][UNIQN];
    __shared__ float h1[32][128];
    const int t = threadIdx.x;
    const int m0 = blockIdx.x * 32;

    for (int l = t; l < 32 * UNIQN; l += 128) {
        int r = l >> 3, c = l & 7;
        int m = m0 + r;
        xs[r][c] = obs[(size_t)(m >> 4) * OBSW + SHRD + (m & 15) * UNIQN + c];
    }
    __syncthreads();

    float acc[32];
#pragma unroll
    for (int r = 0; r < 32; ++r) acc[r] = 0.f;
#pragma unroll
    for (int i = 0; i < UNIQN; ++i) {
        float wv = g_uw1t[i * 128 + t];
#pragma unroll
        for (int r = 0; r < 32; ++r) acc[r] += wv * xs[r][i];
    }
    float b1 = ub1[t];
#pragma unroll
    for (int r = 0; r < 32; ++r) h1[r][t] = fmaxf(acc[r] + b1, 0.f);
    __syncthreads();

#pragma unroll
    for (int r = 0; r < 32; ++r) acc[r] = 0.f;
    for (int k = 0; k < 128; ++k) {
        float wv = g_uw2t[k * 128 + t];
#pragma unroll
        for (int r = 0; r < 32; ++r) acc[r] += wv * h1[r][k];
    }
    float b2 = ub2[t];
    float ne = noop[t];
#pragma unroll
    for (int r = 0; r < 32; ++r) {
        float v = fmaxf(acc[r] + b2, 0.f);
        if (xs[r][0] == 1.0f) v = ne;
        g_ue_h[(size_t)(m0 + r) * 128 + t] = __float2half(v);
    }
}

// ---------------- trunk GEMM: fp16 mma.m16n8k16 + ldmatrix -------------------
// FIRST:  A=[se|ue] (K=384), B=tw1 (N=512), out-> g_t1h (fp16, bias+relu)
// !FIRST: A=g_t1h   (K=512), B=tw2 (N=256), fused heads -> g_pv/g_pd partials
// Block 128x128, BK=32, 8 warps (2m x 4n), warp tile 64x32.
template <bool FIRST>
__global__ __launch_bounds__(256, 2) void gemm_mma(
    const float* __restrict__ bias,
    const float* __restrict__ vw, const float* __restrict__ dw)
{
    constexpr int KD  = FIRST ? 384 : 512;
    constexpr int LDH = 40;                 // padded halfs per smem row
    constexpr int BUFH = 128 * LDH;         // halfs per buffer

    __shared__ __align__(16) __half As[2 * BUFH];
    __shared__ __align__(16) __half Bs[2 * BUFH];
    __shared__ float sbias[128];
    __shared__ float svw[128];
    __shared__ float sdw[128];
    __shared__ float stV[4 * 128];
    __shared__ float stD[4 * 128];

    const __half* __restrict__ Bw = FIRST ? g_tw1h : g_tw2h;

    const int tid  = threadIdx.x;
    const int lane = tid & 31;
    const int wid  = tid >> 5;
    const int wm   = (wid >> 2) * 64;
    const int wn   = (wid & 3) * 32;
    const int mB   = blockIdx.y * 128;
    const int nB   = blockIdx.x * 128;
    const int gID  = lane >> 2;
    const int tIG  = lane & 3;
    const int q    = lane >> 3;
    const int r    = lane & 7;

    if (tid < 128) {
        sbias[tid] = bias[nB + tid];
        if (!FIRST) { svw[tid] = vw[nB + tid]; sdw[tid] = dw[nB + tid]; }
    }

    const uint32_t AsB = (uint32_t)__cvta_generic_to_shared(As);
    const uint32_t BsB = (uint32_t)__cvta_generic_to_shared(Bs);
    // ldmatrix per-lane base byte offsets (within a buffer)
    const uint32_t aOff = ((wm + ((q & 1) << 3) + r) * LDH + ((q >> 1) << 3)) * 2;
    const uint32_t bOff = ((wn + ((q >> 1) << 3) + r) * LDH + ((q & 1) << 3)) * 2;

    float acc[4][4][4] = {};
    uint4 va[2], vb[2];

    // global load mapping: idx = 2*tid + j; row = idx>>2, kq = idx&3 (8 halfs)
    const int mloc = tid >> 1;
    const int gm   = mB + mloc;
    const int nloc = tid >> 1;

    auto loadG = [&](int k0) {
#pragma unroll
        for (int j = 0; j < 2; ++j) {
            int kq = ((tid & 1) << 1) + j;
            int k  = k0 + kq * 8;
            const __half* pa;
            if (FIRST) {
                pa = (k < 256) ? (g_se_h + (size_t)(gm >> 4) * 256 + k)
                               : (g_ue_h + (size_t)gm * 128 + (k - 256));
            } else {
                pa = g_t1h + (size_t)gm * 512 + k;
            }
            va[j] = *(const uint4*)pa;
            vb[j] = *(const uint4*)(Bw + (size_t)(nB + nloc) * KD + k);
        }
    };
    auto storeS = [&](int buf) {
#pragma unroll
        for (int j = 0; j < 2; ++j) {
            int kq = ((tid & 1) << 1) + j;
            *(uint4*)(As + buf * BUFH + mloc * LDH + kq * 8) = va[j];
            *(uint4*)(Bs + buf * BUFH + nloc * LDH + kq * 8) = vb[j];
        }
    };

    loadG(0);
    storeS(0);
    __syncthreads();

    constexpr int nIter = KD / 32;
    for (int it = 0; it < nIter; ++it) {
        const int cur = it & 1;
        if (it + 1 < nIter) loadG((it + 1) * 32);

        const uint32_t aB = AsB + cur * (BUFH * 2) + aOff;
        const uint32_t bB = BsB + cur * (BUFH * 2) + bOff;
#pragma unroll
        for (int ks = 0; ks < 2; ++ks) {
            uint32_t af[4][4], bf[2][4];
#pragma unroll
            for (int mi = 0; mi < 4; ++mi)
                ldmx4(af[mi], aB + mi * (16 * LDH * 2) + ks * 32);
#pragma unroll
            for (int np = 0; np < 2; ++np)
                ldmx4(bf[np], bB + np * (16 * LDH * 2) + ks * 32);
#pragma unroll
            for (int mi = 0; mi < 4; ++mi)
#pragma unroll
                for (int ni = 0; ni < 4; ++ni)
                    mma_f16(acc[mi][ni], af[mi], &bf[ni >> 1][(ni & 1) * 2]);
        }

        if (it + 1 < nIter) storeS(cur ^ 1);
        __syncthreads();
    }

    if constexpr (FIRST) {
        // bias + relu -> fp16 t1
#pragma unroll
        for (int mi = 0; mi < 4; ++mi) {
#pragma unroll
            for (int ni = 0; ni < 4; ++ni) {
                int cl = wn + ni * 8 + 2 * tIG;
                float b0 = sbias[cl], b1 = sbias[cl + 1];
                int row = mB + wm + mi * 16 + gID;
                int col = nB + cl;
                __half2 h0 = __floats2half2_rn(fmaxf(acc[mi][ni][0] + b0, 0.f),
                                               fmaxf(acc[mi][ni][1] + b1, 0.f));
                __half2 h1 = __floats2half2_rn(fmaxf(acc[mi][ni][2] + b0, 0.f),
                                               fmaxf(acc[mi][ni][3] + b1, 0.f));
                *(__half2*)(g_t1h + (size_t)row * 512 + col)       = h0;
                *(__half2*)(g_t1h + (size_t)(row + 8) * 512 + col) = h1;
            }
        }
    } else {
        // fused heads: partial dot over this CTA's 128 cols, full f32 precision
        float pv[8] = {}, pd[8] = {};
#pragma unroll
        for (int mi = 0; mi < 4; ++mi) {
#pragma unroll
            for (int ni = 0; ni < 4; ++ni) {
                int cl = wn + ni * 8 + 2 * tIG;
                float b0 = sbias[cl], b1 = sbias[cl + 1];
                float wv0 = svw[cl], wv1 = svw[cl + 1];
                float wd0 = sdw[cl], wd1 = sdw[cl + 1];
                float t0 = fmaxf(acc[mi][ni][0] + b0, 0.f);
                float t1 = fmaxf(acc[mi][ni][1] + b1, 0.f);
                float t2 = fmaxf(acc[mi][ni][2] + b0, 0.f);
                float t3 = fmaxf(acc[mi][ni][3] + b1, 0.f);
                pv[mi * 2]     += t0 * wv0 + t1 * wv1;
                pd[mi * 2]     += t0 * wd0 + t1 * wd1;
                pv[mi * 2 + 1] += t2 * wv0 + t3 * wv1;
                pd[mi * 2 + 1] += t2 * wd0 + t3 * wd1;
            }
        }
#pragma unroll
        for (int off = 1; off <= 2; off <<= 1) {
#pragma unroll
            for (int i = 0; i < 8; ++i) {
                pv[i] += __shfl_xor_sync(0xffffffffu, pv[i], off);
                pd[i] += __shfl_xor_sync(0xffffffffu, pd[i], off);
            }
        }
        if (tIG == 0) {
#pragma unroll
            for (int mi = 0; mi < 4; ++mi)
#pragma unroll
                for (int rh = 0; rh < 2; ++rh) {
                    int row = wm + mi * 16 + rh * 8 + gID;
                    stV[(wid & 3) * 128 + row] = pv[mi * 2 + rh];
                    stD[(wid & 3) * 128 + row] = pd[mi * 2 + rh];
                }
        }
        __syncthreads();
        if (tid < 128) {
            float v = stV[tid] + stV[128 + tid] + stV[256 + tid] + stV[384 + tid];
            float d = stD[tid] + stD[128 + tid] + stD[256 + tid] + stD[384 + tid];
            size_t o = (size_t)blockIdx.x * MROWS + mB + tid;
            g_pv[o] = v;
            g_pd[o] = d;
        }
    }
}

// ---------------- combine: partials -> logits / duration ---------------------
__global__ __launch_bounds__(256) void combine_kernel(
    const float* __restrict__ vb, const float* __restrict__ db,
    float* __restrict__ out)
{
    int i = blockIdx.x * 256 + threadIdx.x;
    out[i] = g_pv[i] + g_pv[MROWS + i] + vb[0];
    float s = g_pd[i] + g_pd[MROWS + i] + db[0];
    out[MROWS + i] = 1.f / (1.f + expf(-s)) * 0.4f + 0.1f;
}

// ---------------- launch -----------------------------------------------------
extern "C" void kernel_launch(void* const* d_in, const int* in_sizes, int n_in,
                              void* d_out, int out_size)
{
    (void)in_sizes; (void)n_in; (void)out_size;
    const float* obs  = (const float*)d_in[0];
    const float* sw1  = (const float*)d_in[1];
    const float* sb1  = (const float*)d_in[2];
    const float* sw2  = (const float*)d_in[3];
    const float* sb2  = (const float*)d_in[4];
    const float* uw1  = (const float*)d_in[5];
    const float* ub1  = (const float*)d_in[6];
    const float* uw2  = (const float*)d_in[7];
    const float* ub2  = (const float*)d_in[8];
    const float* noop = (const float*)d_in[9];
    const float* tw1  = (const float*)d_in[10];
    const float* tb1  = (const float*)d_in[11];
    const float* tw2  = (const float*)d_in[12];
    const float* tb2  = (const float*)d_in[13];
    const float* vw   = (const float*)d_in[14];
    const float* vb   = (const float*)d_in[15];
    const float* dw   = (const float*)d_in[16];
    const float* db   = (const float*)d_in[17];
    float* out = (float*)d_out;

    prep_kernel<<<768, 256>>>(sw1, sw2, uw1, uw2, tw1, tw2);
    se_kernel<<<BB / 32, 256>>>(obs, sb1, sb2);
    ue_kernel<<<MROWS / 32, 128>>>(obs, ub1, ub2, noop);
    gemm_mma<true><<<dim3(4, MROWS / 128), 256>>>(tb1, nullptr, nullptr);
    gemm_mma<false><<<dim3(2, MROWS / 128), 256>>>(tb2, vw, dw);
    combine_kernel<<<MROWS / 256, 256>>>(vb, db, out);
}

// round 5
// speedup vs baseline: 4.5953x; 1.5352x over previous
#include <cuda_runtime.h>
#include <cuda_fp16.h>
#include <math.h>
#include <stdint.h>

#define BB     8192
#define OPTN   16
#define SHRD   22
#define UNIQN  8
#define OBSW   150
#define MROWS  131072

// ---------------- scratch (device globals) -----------------------------------
__device__ __half g_se_h[BB * 256];                 // 4 MB
__device__ __half g_h1u[(size_t)MROWS * 128];       // 32 MB (ue hidden)
__device__ __half g_ue_h[(size_t)MROWS * 128];      // 32 MB
__device__ __half g_t1h[(size_t)MROWS * 512];       // 128 MB
__device__ __half g_tw1h[512 * 384];                // fp16 weights, [n][k]
__device__ __half g_tw2h[256 * 512];
__device__ __half g_uw2h[128 * 128];
__device__ float  g_pv[2 * MROWS];                  // head partials
__device__ float  g_pd[2 * MROWS];
__device__ float  g_sw1t[22 * 256];
__device__ float  g_sw2t[256 * 256];
__device__ float  g_uw1t[8 * 128];

__device__ __forceinline__ void mma_f16(float* c, const uint32_t* a, const uint32_t* b) {
    asm volatile(
        "mma.sync.aligned.m16n8k16.row.col.f32.f16.f16.f32 "
        "{%0,%1,%2,%3}, {%4,%5,%6,%7}, {%8,%9}, {%0,%1,%2,%3};"
        : "+f"(c[0]), "+f"(c[1]), "+f"(c[2]), "+f"(c[3])
        : "r"(a[0]), "r"(a[1]), "r"(a[2]), "r"(a[3]), "r"(b[0]), "r"(b[1]));
}

__device__ __forceinline__ void ldmx4(uint32_t* r, uint32_t addr) {
    asm volatile("ldmatrix.sync.aligned.m8n8.x4.shared.b16 {%0,%1,%2,%3}, [%4];"
                 : "=r"(r[0]), "=r"(r[1]), "=r"(r[2]), "=r"(r[3]) : "r"(addr));
}

// ---------------- prep -------------------------------------------------------
__global__ __launch_bounds__(256) void prep_kernel(
    const float* __restrict__ sw1, const float* __restrict__ sw2,
    const float* __restrict__ uw1, const float* __restrict__ uw2,
    const float* __restrict__ tw1, const float* __restrict__ tw2)
{
    int idx = blockIdx.x * 256 + threadIdx.x;
    if (idx < 512 * 384) g_tw1h[idx] = __float2half(tw1[idx]);
    if (idx < 256 * 512) g_tw2h[idx] = __float2half(tw2[idx]);
    if (idx < 128 * 128) g_uw2h[idx] = __float2half(uw2[idx]);
    if (idx < 256 * 256) { int o = idx / 256, k = idx - o * 256; g_sw2t[k * 256 + o] = sw2[idx]; }
    if (idx < 256 * 22)  { int o = idx / 22,  i = idx - o * 22;  g_sw1t[i * 256 + o] = sw1[idx]; }
    if (idx < 128 * 8)   { int o = idx / 8,   i = idx - o * 8;   g_uw1t[i * 128 + o] = uw1[idx]; }
}

// ---------------- shared-branch MLP (f32 math, fp16 out) ---------------------
__global__ __launch_bounds__(256) void se_kernel(
    const float* __restrict__ obs,
    const float* __restrict__ sb1, const float* __restrict__ sb2)
{
    __shared__ float xs[32][SHRD];
    __shared__ float h1[32][256];
    const int t = threadIdx.x;
    const int row0 = blockIdx.x * 32;

    for (int l = t; l < 32 * SHRD; l += 256) {
        int r = l / SHRD, c = l - r * SHRD;
        xs[r][c] = obs[(size_t)(row0 + r) * OBSW + c];
    }
    __syncthreads();

    float acc[32];
#pragma unroll
    for (int r = 0; r < 32; ++r) acc[r] = 0.f;
    for (int i = 0; i < SHRD; ++i) {
        float wv = g_sw1t[i * 256 + t];
#pragma unroll
        for (int r = 0; r < 32; ++r) acc[r] += wv * xs[r][i];
    }
    float b1 = sb1[t];
#pragma unroll
    for (int r = 0; r < 32; ++r) h1[r][t] = fmaxf(acc[r] + b1, 0.f);
    __syncthreads();

#pragma unroll
    for (int r = 0; r < 32; ++r) acc[r] = 0.f;
    for (int k = 0; k < 256; ++k) {
        float wv = g_sw2t[k * 256 + t];
#pragma unroll
        for (int r = 0; r < 32; ++r) acc[r] += wv * h1[r][k];
    }
    float b2 = sb2[t];
#pragma unroll
    for (int r = 0; r < 32; ++r)
        g_se_h[(size_t)(row0 + r) * 256 + t] = __float2half(fmaxf(acc[r] + b2, 0.f));
}

// ---------------- ue layer1: (B*OPT, 8) -> 128, fp16 out ---------------------
__global__ __launch_bounds__(128) void ue1_kernel(
    const float* __restrict__ obs, const float* __restrict__ ub1)
{
    __shared__ float xs[32][UNIQN];
    const int t = threadIdx.x;
    const int m0 = blockIdx.x * 32;

    for (int l = t; l < 32 * UNIQN; l += 128) {
        int r = l >> 3, c = l & 7;
        int m = m0 + r;
        xs[r][c] = obs[(size_t)(m >> 4) * OBSW + SHRD + (m & 15) * UNIQN + c];
    }
    __syncthreads();

    float acc[32];
#pragma unroll
    for (int r = 0; r < 32; ++r) acc[r] = 0.f;
#pragma unroll
    for (int i = 0; i < UNIQN; ++i) {
        float wv = g_uw1t[i * 128 + t];
#pragma unroll
        for (int r = 0; r < 32; ++r) acc[r] += wv * xs[r][i];
    }
    float b1 = ub1[t];
#pragma unroll
    for (int r = 0; r < 32; ++r)
        g_h1u[(size_t)(m0 + r) * 128 + t] = __float2half(fmaxf(acc[r] + b1, 0.f));
}

// ---------------- generic fp16 mma GEMM, 4 warps, warp tile 64x64 ------------
// MODE 0 (UE): A=g_h1u (K=128),  B=uw2 (N=128) -> relu+noop-mask -> g_ue_h
// MODE 1 (T1): A=[se|ue](K=384), B=tw1 (N=512) -> relu -> g_t1h
// MODE 2 (T2): A=g_t1h (K=512),  B=tw2 (N=256) -> fused heads -> g_pv/g_pd
template <int MODE>
__global__ __launch_bounds__(128) void gemm_mma(
    const float* __restrict__ bias,
    const float* __restrict__ aux1,   // MODE0: obs, MODE2: vw
    const float* __restrict__ aux2)   // MODE0: no_op_embedding, MODE2: dw
{
    constexpr int KD  = (MODE == 0) ? 128 : (MODE == 1) ? 384 : 512;
    constexpr int LDH = 40;
    constexpr int BUFH = 128 * LDH;

    __shared__ __align__(16) __half As[2 * BUFH];
    __shared__ __align__(16) __half Bs[2 * BUFH];
    __shared__ float sbias[128];
    __shared__ float sx1[128];
    __shared__ float sx2[128];
    __shared__ float stV[2 * 128];
    __shared__ float stD[2 * 128];

    const __half* __restrict__ Bw =
        (MODE == 0) ? g_uw2h : (MODE == 1) ? g_tw1h : g_tw2h;

    const int tid  = threadIdx.x;
    const int lane = tid & 31;
    const int wid  = tid >> 5;
    const int wm   = (wid >> 1) * 64;
    const int wn   = (wid & 1) * 64;
    const int mB   = blockIdx.y * 128;
    const int nB   = blockIdx.x * 128;
    const int gID  = lane >> 2;
    const int tIG  = lane & 3;
    const int q    = lane >> 3;
    const int r    = lane & 7;

    sbias[tid] = bias[nB + tid];
    if (MODE == 0) sx1[tid] = aux2[tid];                 // no_op_embedding
    if (MODE == 2) { sx1[tid] = aux1[nB + tid]; sx2[tid] = aux2[nB + tid]; }

    const uint32_t AsB = (uint32_t)__cvta_generic_to_shared(As);
    const uint32_t BsB = (uint32_t)__cvta_generic_to_shared(Bs);
    const uint32_t aOff = ((wm + ((q & 1) << 3) + r) * LDH + ((q >> 1) << 3)) * 2;
    const uint32_t bOff = ((wn + ((q >> 1) << 3) + r) * LDH + ((q & 1) << 3)) * 2;

    float acc[4][8][4] = {};
    uint4 va[4], vb[4];

    // loader: chunk c = tid + 128*j; row = c>>2 (=tid>>2 + 32*j), kq = c&3
    const int arow = tid >> 2;
    const int kq4  = tid & 3;

    auto loadG = [&](int k0) {
        const int k = k0 + kq4 * 8;
#pragma unroll
        for (int j = 0; j < 4; ++j) {
            int row = arow + 32 * j;
            int gm = mB + row;
            const __half* pa;
            if (MODE == 0)      pa = g_h1u + (size_t)gm * 128 + k;
            else if (MODE == 1) pa = (k < 256) ? (g_se_h + (size_t)(gm >> 4) * 256 + k)
                                               : (g_h1u + 0, g_ue_h + (size_t)gm * 128 + (k - 256));
            else                pa = g_t1h + (size_t)gm * 512 + k;
            va[j] = *(const uint4*)pa;
            vb[j] = *(const uint4*)(Bw + (size_t)(nB + row) * KD + k);
        }
    };
    auto storeS = [&](int buf) {
#pragma unroll
        for (int j = 0; j < 4; ++j) {
            int row = arow + 32 * j;
            *(uint4*)(As + buf * BUFH + row * LDH + kq4 * 8) = va[j];
            *(uint4*)(Bs + buf * BUFH + row * LDH + kq4 * 8) = vb[j];
        }
    };

    loadG(0);
    storeS(0);
    __syncthreads();

    constexpr int nIter = KD / 32;
    for (int it = 0; it < nIter; ++it) {
        const int cur = it & 1;
        if (it + 1 < nIter) loadG((it + 1) * 32);

        const uint32_t aB = AsB + cur * (BUFH * 2) + aOff;
        const uint32_t bB = BsB + cur * (BUFH * 2) + bOff;
#pragma unroll
        for (int ks = 0; ks < 2; ++ks) {
            uint32_t af[4][4], bf[4][4];
#pragma unroll
            for (int mi = 0; mi < 4; ++mi)
                ldmx4(af[mi], aB + mi * (16 * LDH * 2) + ks * 32);
#pragma unroll
            for (int np = 0; np < 4; ++np)
                ldmx4(bf[np], bB + np * (16 * LDH * 2) + ks * 32);
#pragma unroll
            for (int mi = 0; mi < 4; ++mi)
#pragma unroll
                for (int ni = 0; ni < 8; ++ni)
                    mma_f16(acc[mi][ni], af[mi], &bf[ni >> 1][(ni & 1) * 2]);
        }

        if (it + 1 < nIter) storeS(cur ^ 1);
        __syncthreads();
    }

    if constexpr (MODE == 1) {
#pragma unroll
        for (int mi = 0; mi < 4; ++mi) {
#pragma unroll
            for (int ni = 0; ni < 8; ++ni) {
                int cl = wn + ni * 8 + 2 * tIG;
                float b0 = sbias[cl], b1 = sbias[cl + 1];
                int row = mB + wm + mi * 16 + gID;
                int col = nB + cl;
                __half2 h0 = __floats2half2_rn(fmaxf(acc[mi][ni][0] + b0, 0.f),
                                               fmaxf(acc[mi][ni][1] + b1, 0.f));
                __half2 h1 = __floats2half2_rn(fmaxf(acc[mi][ni][2] + b0, 0.f),
                                               fmaxf(acc[mi][ni][3] + b1, 0.f));
                *(__half2*)(g_t1h + (size_t)row * 512 + col)       = h0;
                *(__half2*)(g_t1h + (size_t)(row + 8) * 512 + col) = h1;
            }
        }
    } else if constexpr (MODE == 0) {
        // relu + no-op mask -> g_ue_h
        bool flg[4][2];
#pragma unroll
        for (int mi = 0; mi < 4; ++mi)
#pragma unroll
            for (int rh = 0; rh < 2; ++rh) {
                int row = mB + wm + mi * 16 + rh * 8 + gID;
                float u0 = aux1[(size_t)(row >> 4) * OBSW + SHRD + (row & 15) * UNIQN];
                flg[mi][rh] = (u0 == 1.0f);
            }
#pragma unroll
        for (int mi = 0; mi < 4; ++mi) {
#pragma unroll
            for (int ni = 0; ni < 8; ++ni) {
                int cl = wn + ni * 8 + 2 * tIG;
                float b0 = sbias[cl], b1 = sbias[cl + 1];
                float e0 = sx1[cl], e1 = sx1[cl + 1];
                int row = mB + wm + mi * 16 + gID;
                float v00 = flg[mi][0] ? e0 : fmaxf(acc[mi][ni][0] + b0, 0.f);
                float v01 = flg[mi][0] ? e1 : fmaxf(acc[mi][ni][1] + b1, 0.f);
                float v10 = flg[mi][1] ? e0 : fmaxf(acc[mi][ni][2] + b0, 0.f);
                float v11 = flg[mi][1] ? e1 : fmaxf(acc[mi][ni][3] + b1, 0.f);
                *(__half2*)(g_ue_h + (size_t)row * 128 + cl)       = __floats2half2_rn(v00, v01);
                *(__half2*)(g_ue_h + (size_t)(row + 8) * 128 + cl) = __floats2half2_rn(v10, v11);
            }
        }
    } else {
        // fused heads: partial dots over this CTA's 128 cols
        float pv[8] = {}, pd[8] = {};
#pragma unroll
        for (int mi = 0; mi < 4; ++mi) {
#pragma unroll
            for (int ni = 0; ni < 8; ++ni) {
                int cl = wn + ni * 8 + 2 * tIG;
                float b0 = sbias[cl], b1 = sbias[cl + 1];
                float wv0 = sx1[cl], wv1 = sx1[cl + 1];
                float wd0 = sx2[cl], wd1 = sx2[cl + 1];
                float t0 = fmaxf(acc[mi][ni][0] + b0, 0.f);
                float t1 = fmaxf(acc[mi][ni][1] + b1, 0.f);
                float t2 = fmaxf(acc[mi][ni][2] + b0, 0.f);
                float t3 = fmaxf(acc[mi][ni][3] + b1, 0.f);
                pv[mi * 2]     += t0 * wv0 + t1 * wv1;
                pd[mi * 2]     += t0 * wd0 + t1 * wd1;
                pv[mi * 2 + 1] += t2 * wv0 + t3 * wv1;
                pd[mi * 2 + 1] += t2 * wd0 + t3 * wd1;
            }
        }
#pragma unroll
        for (int off = 1; off <= 2; off <<= 1) {
#pragma unroll
            for (int i = 0; i < 8; ++i) {
                pv[i] += __shfl_xor_sync(0xffffffffu, pv[i], off);
                pd[i] += __shfl_xor_sync(0xffffffffu, pd[i], off);
            }
        }
        if (tIG == 0) {
#pragma unroll
            for (int mi = 0; mi < 4; ++mi)
#pragma unroll
                for (int rh = 0; rh < 2; ++rh) {
                    int row = wm + mi * 16 + rh * 8 + gID;
                    stV[(wid & 1) * 128 + row] = pv[mi * 2 + rh];
                    stD[(wid & 1) * 128 + row] = pd[mi * 2 + rh];
                }
        }
        __syncthreads();
        float v = stV[tid] + stV[128 + tid];
        float d = stD[tid] + stD[128 + tid];
        size_t o = (size_t)blockIdx.x * MROWS + mB + tid;
        g_pv[o] = v;
        g_pd[o] = d;
    }
}

// ---------------- combine: partials -> logits / duration ---------------------
__global__ __launch_bounds__(256) void combine_kernel(
    const float* __restrict__ vb, const float* __restrict__ db,
    float* __restrict__ out)
{
    int i = blockIdx.x * 256 + threadIdx.x;
    out[i] = g_pv[i] + g_pv[MROWS + i] + vb[0];
    float s = g_pd[i] + g_pd[MROWS + i] + db[0];
    out[MROWS + i] = 1.f / (1.f + expf(-s)) * 0.4f + 0.1f;
}

// ---------------- launch -----------------------------------------------------
extern "C" void kernel_launch(void* const* d_in, const int* in_sizes, int n_in,
                              void* d_out, int out_size)
{
    (void)in_sizes; (void)n_in; (void)out_size;
    const float* obs  = (const float*)d_in[0];
    const float* sw1  = (const float*)d_in[1];
    const float* sb1  = (const float*)d_in[2];
    const float* sw2  = (const float*)d_in[3];
    const float* sb2  = (const float*)d_in[4];
    const float* uw1  = (const float*)d_in[5];
    const float* ub1  = (const float*)d_in[6];
    const float* uw2  = (const float*)d_in[7];
    const float* ub2  = (const float*)d_in[8];
    const float* noop = (const float*)d_in[9];
    const float* tw1  = (const float*)d_in[10];
    const float* tb1  = (const float*)d_in[11];
    const float* tw2  = (const float*)d_in[12];
    const float* tb2  = (const float*)d_in[13];
    const float* vw   = (const float*)d_in[14];
    const float* vb   = (const float*)d_in[15];
    const float* dw   = (const float*)d_in[16];
    const float* db   = (const float*)d_in[17];
    float* out = (float*)d_out;

    prep_kernel<<<768, 256>>>(sw1, sw2, uw1, uw2, tw1, tw2);
    se_kernel<<<BB / 32, 256>>>(obs, sb1, sb2);
    ue1_kernel<<<MROWS / 32, 128>>>(obs, ub1);
    gemm_mma<0><<<dim3(1, MROWS / 128), 128>>>(ub2, obs, noop);
    gemm_mma<1><<<dim3(4, MROWS / 128), 128>>>(tb1, nullptr, nullptr);
    gemm_mma<2><<<dim3(2, MROWS / 128), 128>>>(tb2, vw, dw);
    combine_kernel<<<MROWS / 256, 256>>>(vb, db, out);
}